// round 16
// baseline (speedup 1.0000x reference)
#include <cuda_runtime.h>
#include <cstdint>

#define T_STEPS 128
#define BATCH   64
#define VDIM    2048
#define HDIM    1024
#define GDIM    4096   // 4*H

#define NCTA    128    // persistent CTAs (one per 8 hidden units)
#define NTHR    512    // 16 warps: 4 (M) x 2 (N/gate-pair) x 2 (K-split)

// ---------------- scratch (static device globals; no allocation) ----------
__device__ float g_gates[(size_t)T_STEPS * BATCH * GDIM];  // 134 MB: x@Wi + b
__device__ float g_h[2][BATCH * HDIM];
__device__ float g_c[2][BATCH * HDIM];
__device__ int   g_eos[2][BATCH];
__device__ unsigned g_arrive[NCTA];   // distributed barrier: per-CTA arrival
__device__ unsigned g_gen2;           // distributed barrier: release counter

// ---------------- helpers ------------------------------------------------
__device__ __forceinline__ uint32_t f2tf32(float f) {
    uint32_t r;
    asm("cvt.rna.tf32.f32 %0, %1;" : "=r"(r) : "f"(f));
    return r;
}

__device__ __forceinline__ void st_tf32_4(uint32_t* d, float4 v) {
    uint4 u;
    u.x = f2tf32(v.x); u.y = f2tf32(v.y); u.z = f2tf32(v.z); u.w = f2tf32(v.w);
    *(uint4*)d = u;
}

__device__ __forceinline__ void mma_tf32(float c[4],
                                         uint32_t a0, uint32_t a1, uint32_t a2, uint32_t a3,
                                         uint32_t b0, uint32_t b1) {
    asm volatile(
        "mma.sync.aligned.m16n8k8.row.col.f32.tf32.tf32.f32 "
        "{%0,%1,%2,%3}, {%4,%5,%6,%7}, {%8,%9}, {%0,%1,%2,%3};\n"
        : "+f"(c[0]), "+f"(c[1]), "+f"(c[2]), "+f"(c[3])
        : "r"(a0), "r"(a1), "r"(a2), "r"(a3), "r"(b0), "r"(b1));
}

__device__ __forceinline__ float sigf(float x) {
    return 1.0f / (1.0f + expf(-x));
}

__device__ __forceinline__ void cpa16(void* dst_smem, const void* src_glob) {
    uint32_t d = (uint32_t)__cvta_generic_to_shared(dst_smem);
    asm volatile("cp.async.cg.shared.global [%0], [%1], 16;\n" :: "r"(d), "l"(src_glob));
}
#define CP_COMMIT() asm volatile("cp.async.commit_group;\n" ::: "memory")
#define CP_WAIT2()  asm volatile("cp.async.wait_group 2;\n" ::: "memory")

__device__ __forceinline__ void pfL2(const void* p) {
    asm volatile("prefetch.global.L2 [%0];\n" :: "l"(p));
}

// ---------------- init state ---------------------------------------------
__global__ void init_state(const float* __restrict__ c0,
                           const float* __restrict__ h0,
                           const unsigned char* __restrict__ eos0) {
    int i = blockIdx.x * blockDim.x + threadIdx.x;
    if (i < BATCH * HDIM) {
        g_c[0][i] = c0[i];
        g_h[0][i] = h0[i];
    }
    if (i < BATCH) g_eos[0][i] = eos0[i] ? 1 : 0;
    if (i < NCTA) g_arrive[i] = 0;
    if (i == 0) g_gen2 = 0;
}

// ---------------- phase 1: gates_x = X @ Wi + b  (round-4/10 proven) -------
#define G1_BM 128
#define G1_BN 128
#define G1_BK 16
#define G1_ASTR 20
#define G1_BSTR 132

__global__ __launch_bounds__(256) void gemm1(const float* __restrict__ X,
                                             const float* __restrict__ Wi,
                                             const float* __restrict__ bias) {
    __shared__ uint32_t As[2][G1_BM * G1_ASTR];
    __shared__ uint32_t Bs[2][G1_BK * G1_BSTR];

    const int tid  = threadIdx.x;
    const int lane = tid & 31;
    const int wid  = tid >> 5;
    const int wm   = (wid >> 1) * 32;
    const int wn   = (wid & 1) * 64;
    const int lq   = lane >> 2;
    const int lr   = lane & 3;

    const int m0 = blockIdx.y * G1_BM;
    const int n0 = blockIdx.x * G1_BN;

    float acc[2][8][4];
#pragma unroll
    for (int mi = 0; mi < 2; mi++)
#pragma unroll
        for (int ni = 0; ni < 8; ni++)
#pragma unroll
            for (int q = 0; q < 4; q++) acc[mi][ni][q] = 0.0f;

    const int ar = tid >> 1;
    const int ac = (tid & 1) * 8;
    const int br = tid >> 4;
    const int bc = (tid & 15) * 8;

    const float* asrc = X  + (size_t)(m0 + ar) * VDIM + ac;
    const float* bsrc = Wi + (size_t)br * GDIM + n0 + bc;

    float4 av0 = *(const float4*)(asrc);
    float4 av1 = *(const float4*)(asrc + 4);
    float4 bv0 = *(const float4*)(bsrc);
    float4 bv1 = *(const float4*)(bsrc + 4);

    const int NIT = VDIM / G1_BK;   // 128
    for (int it = 0; it < NIT; it++) {
        const int p = it & 1;
        st_tf32_4(&As[p][ar * G1_ASTR + ac],     av0);
        st_tf32_4(&As[p][ar * G1_ASTR + ac + 4], av1);
        st_tf32_4(&Bs[p][br * G1_BSTR + bc],     bv0);
        st_tf32_4(&Bs[p][br * G1_BSTR + bc + 4], bv1);
        __syncthreads();

        if (it + 1 < NIT) {
            int k1 = (it + 1) * G1_BK;
            av0 = *(const float4*)(asrc + k1);
            av1 = *(const float4*)(asrc + k1 + 4);
            bv0 = *(const float4*)(bsrc + (size_t)k1 * GDIM);
            bv1 = *(const float4*)(bsrc + (size_t)k1 * GDIM + 4);
        }

        const uint32_t* as = As[p];
        const uint32_t* bs = Bs[p];
#pragma unroll
        for (int kk = 0; kk < G1_BK; kk += 8) {
            uint32_t afr[2][4];
#pragma unroll
            for (int mi = 0; mi < 2; mi++) {
                int r = wm + mi * 16 + lq;
                afr[mi][0] = as[r * G1_ASTR + kk + lr];
                afr[mi][1] = as[(r + 8) * G1_ASTR + kk + lr];
                afr[mi][2] = as[r * G1_ASTR + kk + lr + 4];
                afr[mi][3] = as[(r + 8) * G1_ASTR + kk + lr + 4];
            }
            uint32_t bfr[8][2];
#pragma unroll
            for (int ni = 0; ni < 8; ni++) {
                int c = wn + ni * 8 + lq;
                bfr[ni][0] = bs[(kk + lr) * G1_BSTR + c];
                bfr[ni][1] = bs[(kk + lr + 4) * G1_BSTR + c];
            }
#pragma unroll
            for (int mi = 0; mi < 2; mi++)
#pragma unroll
                for (int ni = 0; ni < 8; ni++)
                    mma_tf32(acc[mi][ni], afr[mi][0], afr[mi][1], afr[mi][2], afr[mi][3],
                             bfr[ni][0], bfr[ni][1]);
        }
    }

#pragma unroll
    for (int mi = 0; mi < 2; mi++) {
#pragma unroll
        for (int ni = 0; ni < 8; ni++) {
            int r0 = m0 + wm + mi * 16 + lq;
            int c0 = n0 + wn + ni * 8 + 2 * lr;
            float bl = bias[c0];
            float bh = bias[c0 + 1];
            g_gates[(size_t)r0 * GDIM + c0]           = acc[mi][ni][0] + bl;
            g_gates[(size_t)r0 * GDIM + c0 + 1]       = acc[mi][ni][1] + bh;
            g_gates[(size_t)(r0 + 8) * GDIM + c0]     = acc[mi][ni][2] + bl;
            g_gates[(size_t)(r0 + 8) * GDIM + c0 + 1] = acc[mi][ni][3] + bh;
        }
    }
}

// ---------------- phase 2: persistent recurrent kernel ---------------------
// R15 logic; ONLY change: distributed flag barrier (parallel per-CTA arrival
// stores + CTA0 aggregation) replacing the serialized single-counter atomic.
#define NSTG 4
#define WS_STR 36
#define HS_STR 36
#define GS_STR 34
#define WS_WORDS (HDIM * WS_STR)                // 36864
#define HS_WORDS (NSTG * BATCH * HS_STR)        // 9216
#define GS_WORDS (2 * BATCH * GS_STR)           // 4352
#define PSMEM_BYTES ((WS_WORDS + HS_WORDS + GS_WORDS) * 4) // 201728 B

// Distributed barrier: monotonic per-CTA flags, CTA0 aggregates, publishes gen.
// No resets -> no ABA. CTA0's extra __syncthreads is CTA-local (safe).
__device__ __forceinline__ void grid_barrier(int t, int j) {
    const int tid = threadIdx.x;
    const unsigned gen = (unsigned)(t + 1);
    __syncthreads();
    if (tid == 0) {
        __threadfence();                       // release this CTA's stores
        ((volatile unsigned*)g_arrive)[j] = gen;
    }
    if (j == 0) {
        if (tid < NCTA) {
            while (((volatile unsigned*)g_arrive)[tid] < gen) { }
        }
        __syncthreads();
        if (tid == 0) {
            __threadfence();
            *(volatile unsigned*)&g_gen2 = gen;
        }
    }
    if (tid == 0) {
        while (*(volatile unsigned*)&g_gen2 < gen) { }
        __threadfence();                       // acquire
    }
    __syncthreads();
}

__global__ __launch_bounds__(NTHR) void lstm_persist(const float* __restrict__ X,
                                                     const float* __restrict__ Wh,
                                                     float* __restrict__ ys) {
    extern __shared__ uint32_t dsm[];
    uint32_t* ws  = dsm;                       // [1024][36] Wh slice (tf32)
    float*    hs  = (float*)(dsm + WS_WORDS);  // [4][64][36] h tiles (float)
    float*    gsm = (float*)(dsm + WS_WORDS + HS_WORDS); // [2][64][34] partials

    const int tid  = threadIdx.x;
    const int lane = tid & 31;
    const int w    = tid >> 5;        // warp 0..15
    const int lq   = lane >> 2;
    const int lr   = lane & 3;
    const int j    = blockIdx.x;      // hidden slice

    const int kh   = w >> 3;          // k-half: kk in {0,8} or {16,24}
    const int wm16 = ((w >> 1) & 3) * 16;  // M offset: 4 splits of 16 rows
    const int wn   = w & 1;           // N half: gates {0,1} or {2,3}

    // ---- preload Wh slice into SMEM once (converted to tf32) ----
    {
        const int rr = tid >> 3;
        const int q  = tid & 7;
        const int g  = q >> 1;
        const int half = q & 1;
        for (int base = 0; base < HDIM; base += 64) {
            float4 v = *(const float4*)(Wh + (size_t)(base + rr) * GDIM + g * HDIM + j * 8 + half * 4);
            st_tf32_4(ws + (base + rr) * WS_STR + q * 4, v);
        }
    }
    __syncthreads();

    // h staging map: 512 threads, row = tid>>3 (0..63), 4 floats each
    const int hr = tid >> 3;
    const int hc = (tid & 7) * 4;
    const int NIT = HDIM / 32;        // 32 k-tiles per step

    // epilogue map: one output per thread
    const int er = tid >> 3;          // batch row 0..63
    const int eu = tid & 7;           // hidden unit 0..7

    for (int t = 0; t < T_STEPS; t++) {
        const int cur = t & 1;
        const int nxt = cur ^ 1;
        const float* hprev = g_h[cur];
        const float* cprev = g_c[cur];
        float* hnex = g_h[nxt];
        float* cnex = g_c[nxt];
        const float* gx = g_gates + (size_t)t * BATCH * GDIM;

        // ---- L2 prefetch of this step's epilogue gate operands ----
        {
            const float* gp = gx + (size_t)er * GDIM + j * 8 + eu;
            pfL2(gp);
            pfL2(gp + HDIM);
            pfL2(gp + 2 * HDIM);
            pfL2(gp + 3 * HDIM);
        }

        float acc[2][4];                       // [ni][frag], 2 gate cols of 8
#pragma unroll
        for (int ni = 0; ni < 2; ni++)
#pragma unroll
            for (int q = 0; q < 4; q++) acc[ni][q] = 0.0f;

        // ---- cp.async pipeline prologue: stages 0,1,2 ----
#pragma unroll
        for (int s = 0; s < 3; s++) {
            float* hb = hs + s * (BATCH * HS_STR);
            cpa16(hb + hr * HS_STR + hc, hprev + (size_t)hr * HDIM + s * 32 + hc);
            CP_COMMIT();
        }

        for (int it = 0; it < NIT; it++) {
            CP_WAIT2();          // oldest of 3 pending groups (tile it) done
            __syncthreads();

            if (it + 3 < NIT) {
                float* hb2 = hs + ((it + 3) % NSTG) * (BATCH * HS_STR);
                cpa16(hb2 + hr * HS_STR + hc, hprev + (size_t)hr * HDIM + (it + 3) * 32 + hc);
            }
            CP_COMMIT();

            const float* hb = hs + (it % NSTG) * (BATCH * HS_STR);
            const int k0 = it * 32;
#pragma unroll
            for (int ks = 0; ks < 2; ks++) {
                const int kk = kh * 16 + ks * 8;
                int r = wm16 + lq;
                uint32_t a0 = f2tf32(hb[r * HS_STR + kk + lr]);
                uint32_t a1 = f2tf32(hb[(r + 8) * HS_STR + kk + lr]);
                uint32_t a2 = f2tf32(hb[r * HS_STR + kk + lr + 4]);
                uint32_t a3 = f2tf32(hb[(r + 8) * HS_STR + kk + lr + 4]);
#pragma unroll
                for (int ni = 0; ni < 2; ni++) {
                    int g = wn * 2 + ni;       // gate 0..3
                    uint32_t b0 = ws[(k0 + kk + lr) * WS_STR + g * 8 + lq];
                    uint32_t b1 = ws[(k0 + kk + lr + 4) * WS_STR + g * 8 + lq];
                    mma_tf32(acc[ni], a0, a1, a2, a3, b0, b1);
                }
            }
        }

        // ---- exchange: dump warp partials to gsm[kh][64][34] ----
        {
            float* gs = gsm + kh * (BATCH * GS_STR);
#pragma unroll
            for (int ni = 0; ni < 2; ni++) {
                int col = (wn * 2 + ni) * 8 + 2 * lr;
                int row = wm16 + lq;
                gs[row * GS_STR + col]           = acc[ni][0];
                gs[row * GS_STR + col + 1]       = acc[ni][1];
                gs[(row + 8) * GS_STR + col]     = acc[ni][2];
                gs[(row + 8) * GS_STR + col + 1] = acc[ni][3];
            }
        }
        __syncthreads();

        // ---- cell epilogue: one output per thread (512 outputs) ----
        {
            const int r = er, u = eu;
            const int hcol = j * 8 + u;
            const float* g0 = gsm + r * GS_STR;
            const float* g1 = gsm + BATCH * GS_STR + r * GS_STR;

            bool m = (__ldcg(&g_eos[cur][r]) != 0);
            const float* gp = gx + (size_t)r * GDIM + hcol;
            float iv = g0[u]      + g1[u]      + __ldg(gp);
            float fv = g0[8 + u]  + g1[8 + u]  + __ldg(gp + HDIM);
            float gv = g0[16 + u] + g1[16 + u] + __ldg(gp + 2 * HDIM);
            float ov = g0[24 + u] + g1[24 + u] + __ldg(gp + 3 * HDIM);

            float cp  = __ldcg(cprev + (size_t)r * HDIM + hcol);
            float ncv = sigf(fv) * cp + sigf(iv) * tanhf(gv);
            float nhv = sigf(ov) * tanhf(ncv);

            ys[((size_t)t * BATCH + r) * HDIM + hcol] = nhv;   // unmasked
            cnex[(size_t)r * HDIM + hcol] = m ? cp : ncv;
            hnex[(size_t)r * HDIM + hcol] = m ? __ldcg(hprev + (size_t)r * HDIM + hcol) : nhv;
        }

        if (blockIdx.x == 0 && tid < BATCH) {
            float xe = __ldg(X + ((size_t)t * BATCH + tid) * VDIM + 1);
            int eo = __ldcg(&g_eos[cur][tid]);
            g_eos[nxt][tid] = (eo != 0 || xe != 0.0f) ? 1 : 0;
        }

        grid_barrier(t, j);   // protects gsm/hs reuse and state hand-off
    }
}

// ---------------- launch ---------------------------------------------------
extern "C" void kernel_launch(void* const* d_in, const int* in_sizes, int n_in,
                              void* d_out, int out_size) {
    const float* x  = (const float*)d_in[0];
    const float* Wi = (const float*)d_in[1];
    const float* Wh = (const float*)d_in[2];
    const float* b  = (const float*)d_in[3];
    const float* c0 = (const float*)d_in[4];
    const float* h0 = (const float*)d_in[5];
    const unsigned char* eos0 = (const unsigned char*)d_in[6];
    float* ys = (float*)d_out;

    static bool attr_done = false;
    if (!attr_done) {
        cudaFuncSetAttribute(lstm_persist,
                             cudaFuncAttributeMaxDynamicSharedMemorySize, PSMEM_BYTES);
        attr_done = true;
    }

    init_state<<<(BATCH * HDIM + 255) / 256, 256>>>(c0, h0, eos0);

    dim3 g1(GDIM / G1_BN, (T_STEPS * BATCH) / G1_BM);   // 32 x 64
    gemm1<<<g1, 256>>>(x, Wi, b);

    lstm_persist<<<NCTA, NTHR, PSMEM_BYTES>>>(x, Wh, ys);
}

// round 17
// speedup vs baseline: 1.0649x; 1.0649x over previous
#include <cuda_runtime.h>
#include <cstdint>

#define T_STEPS 128
#define BATCH   64
#define VDIM    2048
#define HDIM    1024
#define GDIM    4096   // 4*H

#define NCTA    128    // persistent CTAs (one per 8 hidden units)
#define NTHR    512    // 16 warps: 4 (K-quarter) x 2 (M-half) x 2 (gate-pair)

// ---------------- scratch (static device globals; no allocation) ----------
__device__ float g_gates[(size_t)T_STEPS * BATCH * GDIM];  // 134 MB: x@Wi + b
__device__ float g_h[2][BATCH * HDIM];   // tf32 bit patterns (quantized once)
__device__ float g_c[2][BATCH * HDIM];
__device__ int   g_eos[2][BATCH];
__device__ unsigned g_bar_count;
__device__ volatile unsigned g_bar_gen;

// ---------------- helpers ------------------------------------------------
__device__ __forceinline__ uint32_t f2tf32(float f) {
    uint32_t r;
    asm("cvt.rna.tf32.f32 %0, %1;" : "=r"(r) : "f"(f));
    return r;
}

__device__ __forceinline__ void st_tf32_4(uint32_t* d, float4 v) {
    uint4 u;
    u.x = f2tf32(v.x); u.y = f2tf32(v.y); u.z = f2tf32(v.z); u.w = f2tf32(v.w);
    *(uint4*)d = u;
}

__device__ __forceinline__ void mma_tf32(float c[4],
                                         uint32_t a0, uint32_t a1, uint32_t a2, uint32_t a3,
                                         uint32_t b0, uint32_t b1) {
    asm volatile(
        "mma.sync.aligned.m16n8k8.row.col.f32.tf32.tf32.f32 "
        "{%0,%1,%2,%3}, {%4,%5,%6,%7}, {%8,%9}, {%0,%1,%2,%3};\n"
        : "+f"(c[0]), "+f"(c[1]), "+f"(c[2]), "+f"(c[3])
        : "r"(a0), "r"(a1), "r"(a2), "r"(a3), "r"(b0), "r"(b1));
}

__device__ __forceinline__ float sigf(float x) {
    return 1.0f / (1.0f + expf(-x));
}

__device__ __forceinline__ void cpa16(void* dst_smem, const void* src_glob) {
    uint32_t d = (uint32_t)__cvta_generic_to_shared(dst_smem);
    asm volatile("cp.async.cg.shared.global [%0], [%1], 16;\n" :: "r"(d), "l"(src_glob));
}
#define CP_COMMIT() asm volatile("cp.async.commit_group;\n" ::: "memory")
#define CP_WAIT2()  asm volatile("cp.async.wait_group 2;\n" ::: "memory")

__device__ __forceinline__ void pfL2(const void* p) {
    asm volatile("prefetch.global.L2 [%0];\n" :: "l"(p));
}

// ---------------- init state ---------------------------------------------
__global__ void init_state(const float* __restrict__ c0,
                           const float* __restrict__ h0,
                           const unsigned char* __restrict__ eos0) {
    int i = blockIdx.x * blockDim.x + threadIdx.x;
    if (i < BATCH * HDIM) {
        g_c[0][i] = c0[i];
        g_h[0][i] = __uint_as_float(f2tf32(h0[i]));   // pre-quantized h state
    }
    if (i < BATCH) g_eos[0][i] = eos0[i] ? 1 : 0;
    if (i == 0) { g_bar_count = 0; g_bar_gen = 0; }
}

// ---------------- phase 1: gates_x = X @ Wi + b  (round-4/10 proven) -------
#define G1_BM 128
#define G1_BN 128
#define G1_BK 16
#define G1_ASTR 20
#define G1_BSTR 132

__global__ __launch_bounds__(256) void gemm1(const float* __restrict__ X,
                                             const float* __restrict__ Wi,
                                             const float* __restrict__ bias) {
    __shared__ uint32_t As[2][G1_BM * G1_ASTR];
    __shared__ uint32_t Bs[2][G1_BK * G1_BSTR];

    const int tid  = threadIdx.x;
    const int lane = tid & 31;
    const int wid  = tid >> 5;
    const int wm   = (wid >> 1) * 32;
    const int wn   = (wid & 1) * 64;
    const int lq   = lane >> 2;
    const int lr   = lane & 3;

    const int m0 = blockIdx.y * G1_BM;
    const int n0 = blockIdx.x * G1_BN;

    float acc[2][8][4];
#pragma unroll
    for (int mi = 0; mi < 2; mi++)
#pragma unroll
        for (int ni = 0; ni < 8; ni++)
#pragma unroll
            for (int q = 0; q < 4; q++) acc[mi][ni][q] = 0.0f;

    const int ar = tid >> 1;
    const int ac = (tid & 1) * 8;
    const int br = tid >> 4;
    const int bc = (tid & 15) * 8;

    const float* asrc = X  + (size_t)(m0 + ar) * VDIM + ac;
    const float* bsrc = Wi + (size_t)br * GDIM + n0 + bc;

    float4 av0 = *(const float4*)(asrc);
    float4 av1 = *(const float4*)(asrc + 4);
    float4 bv0 = *(const float4*)(bsrc);
    float4 bv1 = *(const float4*)(bsrc + 4);

    const int NIT = VDIM / G1_BK;   // 128
    for (int it = 0; it < NIT; it++) {
        const int p = it & 1;
        st_tf32_4(&As[p][ar * G1_ASTR + ac],     av0);
        st_tf32_4(&As[p][ar * G1_ASTR + ac + 4], av1);
        st_tf32_4(&Bs[p][br * G1_BSTR + bc],     bv0);
        st_tf32_4(&Bs[p][br * G1_BSTR + bc + 4], bv1);
        __syncthreads();

        if (it + 1 < NIT) {
            int k1 = (it + 1) * G1_BK;
            av0 = *(const float4*)(asrc + k1);
            av1 = *(const float4*)(asrc + k1 + 4);
            bv0 = *(const float4*)(bsrc + (size_t)k1 * GDIM);
            bv1 = *(const float4*)(bsrc + (size_t)k1 * GDIM + 4);
        }

        const uint32_t* as = As[p];
        const uint32_t* bs = Bs[p];
#pragma unroll
        for (int kk = 0; kk < G1_BK; kk += 8) {
            uint32_t afr[2][4];
#pragma unroll
            for (int mi = 0; mi < 2; mi++) {
                int r = wm + mi * 16 + lq;
                afr[mi][0] = as[r * G1_ASTR + kk + lr];
                afr[mi][1] = as[(r + 8) * G1_ASTR + kk + lr];
                afr[mi][2] = as[r * G1_ASTR + kk + lr + 4];
                afr[mi][3] = as[(r + 8) * G1_ASTR + kk + lr + 4];
            }
            uint32_t bfr[8][2];
#pragma unroll
            for (int ni = 0; ni < 8; ni++) {
                int c = wn + ni * 8 + lq;
                bfr[ni][0] = bs[(kk + lr) * G1_BSTR + c];
                bfr[ni][1] = bs[(kk + lr + 4) * G1_BSTR + c];
            }
#pragma unroll
            for (int mi = 0; mi < 2; mi++)
#pragma unroll
                for (int ni = 0; ni < 8; ni++)
                    mma_tf32(acc[mi][ni], afr[mi][0], afr[mi][1], afr[mi][2], afr[mi][3],
                             bfr[ni][0], bfr[ni][1]);
        }
    }

#pragma unroll
    for (int mi = 0; mi < 2; mi++) {
#pragma unroll
        for (int ni = 0; ni < 8; ni++) {
            int r0 = m0 + wm + mi * 16 + lq;
            int c0 = n0 + wn + ni * 8 + 2 * lr;
            float bl = bias[c0];
            float bh = bias[c0 + 1];
            g_gates[(size_t)r0 * GDIM + c0]           = acc[mi][ni][0] + bl;
            g_gates[(size_t)r0 * GDIM + c0 + 1]       = acc[mi][ni][1] + bh;
            g_gates[(size_t)(r0 + 8) * GDIM + c0]     = acc[mi][ni][2] + bl;
            g_gates[(size_t)(r0 + 8) * GDIM + c0 + 1] = acc[mi][ni][3] + bh;
        }
    }
}

// ---------------- phase 2: persistent recurrent kernel ---------------------
// R15 base; changes: (1) g_h holds tf32 bit patterns -> no cvt in inner loop;
// (2) warp grid 4(Kq) x 2(Mh) x 2(Gp): B-frags amortized over 2 M-frags
// (12 LDS + 4 MMA per tile per warp), 4-way k-partial exchange.
#define NSTG 4
#define WS_STR 36
#define HS_STR 36
#define GS_STR 34
#define WS_WORDS (HDIM * WS_STR)                // 36864
#define HS_WORDS (NSTG * BATCH * HS_STR)        // 9216
#define GS_WORDS (4 * BATCH * GS_STR)           // 8704 (four k-quarter buffers)
#define PSMEM_BYTES ((WS_WORDS + HS_WORDS + GS_WORDS) * 4) // 219136 B

__device__ __forceinline__ void grid_barrier() {
    __syncthreads();
    if (threadIdx.x == 0) {
        __threadfence();
        unsigned gen = g_bar_gen;
        unsigned t = atomicAdd(&g_bar_count, 1u);
        if (t == NCTA - 1) {
            g_bar_count = 0;
            __threadfence();
            g_bar_gen = gen + 1;
        } else {
            while (g_bar_gen == gen) { }
            __threadfence();
        }
    }
    __syncthreads();
}

__global__ __launch_bounds__(NTHR) void lstm_persist(const float* __restrict__ X,
                                                     const float* __restrict__ Wh,
                                                     float* __restrict__ ys) {
    extern __shared__ uint32_t dsm[];
    uint32_t* ws  = dsm;                       // [1024][36] Wh slice (tf32)
    float*    hs  = (float*)(dsm + WS_WORDS);  // [4][64][36] h tiles (tf32 bits)
    float*    gsm = (float*)(dsm + WS_WORDS + HS_WORDS); // [4][64][34] partials

    const int tid  = threadIdx.x;
    const int lane = tid & 31;
    const int w    = tid >> 5;        // warp 0..15
    const int lq   = lane >> 2;
    const int lr   = lane & 3;
    const int j    = blockIdx.x;      // hidden slice

    const int kq = w >> 2;            // k-quarter: kk = kq*8 within 32-k tile
    const int mh = (w >> 1) & 1;      // M half: rows mh*32 .. +32
    const int gp = w & 1;             // gate pair: gates {2gp, 2gp+1}

    // ---- preload Wh slice into SMEM once (converted to tf32) ----
    {
        const int rr = tid >> 3;
        const int q  = tid & 7;
        const int g  = q >> 1;
        const int half = q & 1;
        for (int base = 0; base < HDIM; base += 64) {
            float4 v = *(const float4*)(Wh + (size_t)(base + rr) * GDIM + g * HDIM + j * 8 + half * 4);
            st_tf32_4(ws + (base + rr) * WS_STR + q * 4, v);
        }
    }
    __syncthreads();

    // h staging map: 512 threads, row = tid>>3 (0..63), 4 floats each
    const int hr = tid >> 3;
    const int hc = (tid & 7) * 4;
    const int NIT = HDIM / 32;        // 32 k-tiles per step

    // epilogue map: one output per thread
    const int er = tid >> 3;          // batch row 0..63
    const int eu = tid & 7;           // hidden unit 0..7

    for (int t = 0; t < T_STEPS; t++) {
        const int cur = t & 1;
        const int nxt = cur ^ 1;
        const float* hprev = g_h[cur];
        const float* cprev = g_c[cur];
        float* hnex = g_h[nxt];
        float* cnex = g_c[nxt];
        const float* gx = g_gates + (size_t)t * BATCH * GDIM;

        // ---- L2 prefetch of this step's epilogue gate operands ----
        {
            const float* gp2 = gx + (size_t)er * GDIM + j * 8 + eu;
            pfL2(gp2);
            pfL2(gp2 + HDIM);
            pfL2(gp2 + 2 * HDIM);
            pfL2(gp2 + 3 * HDIM);
        }

        float acc[2][2][4];               // [mi][ni][frag]
#pragma unroll
        for (int mi = 0; mi < 2; mi++)
#pragma unroll
            for (int ni = 0; ni < 2; ni++)
#pragma unroll
                for (int q = 0; q < 4; q++) acc[mi][ni][q] = 0.0f;

        // ---- cp.async pipeline prologue: stages 0,1,2 ----
#pragma unroll
        for (int s = 0; s < 3; s++) {
            float* hb = hs + s * (BATCH * HS_STR);
            cpa16(hb + hr * HS_STR + hc, hprev + (size_t)hr * HDIM + s * 32 + hc);
            CP_COMMIT();
        }

        for (int it = 0; it < NIT; it++) {
            CP_WAIT2();          // oldest of 3 pending groups (tile it) done
            __syncthreads();

            if (it + 3 < NIT) {
                float* hb2 = hs + ((it + 3) % NSTG) * (BATCH * HS_STR);
                cpa16(hb2 + hr * HS_STR + hc, hprev + (size_t)hr * HDIM + (it + 3) * 32 + hc);
            }
            CP_COMMIT();

            const float* hb = hs + (it % NSTG) * (BATCH * HS_STR);
            const int k0 = it * 32;
            const int kk = kq * 8;
            // A fragments: 2 M-subfrags (rows mh*32+{0,16}+lq), tf32 bits
            uint32_t a[2][4];
#pragma unroll
            for (int mi = 0; mi < 2; mi++) {
                int r = mh * 32 + mi * 16 + lq;
                a[mi][0] = __float_as_uint(hb[r * HS_STR + kk + lr]);
                a[mi][1] = __float_as_uint(hb[(r + 8) * HS_STR + kk + lr]);
                a[mi][2] = __float_as_uint(hb[r * HS_STR + kk + lr + 4]);
                a[mi][3] = __float_as_uint(hb[(r + 8) * HS_STR + kk + lr + 4]);
            }
#pragma unroll
            for (int ni = 0; ni < 2; ni++) {
                int g = gp * 2 + ni;       // gate 0..3
                uint32_t b0 = ws[(k0 + kk + lr) * WS_STR + g * 8 + lq];
                uint32_t b1 = ws[(k0 + kk + lr + 4) * WS_STR + g * 8 + lq];
#pragma unroll
                for (int mi = 0; mi < 2; mi++)
                    mma_tf32(acc[mi][ni], a[mi][0], a[mi][1], a[mi][2], a[mi][3], b0, b1);
            }
        }

        // ---- exchange: dump warp partials to gsm[kq][64][34] ----
        {
            float* gs = gsm + kq * (BATCH * GS_STR);
#pragma unroll
            for (int mi = 0; mi < 2; mi++) {
#pragma unroll
                for (int ni = 0; ni < 2; ni++) {
                    int col = (gp * 2 + ni) * 8 + 2 * lr;
                    int row = mh * 32 + mi * 16 + lq;
                    gs[row * GS_STR + col]           = acc[mi][ni][0];
                    gs[row * GS_STR + col + 1]       = acc[mi][ni][1];
                    gs[(row + 8) * GS_STR + col]     = acc[mi][ni][2];
                    gs[(row + 8) * GS_STR + col + 1] = acc[mi][ni][3];
                }
            }
        }
        __syncthreads();

        // ---- cell epilogue: one output per thread (512 outputs) ----
        {
            const int r = er, u = eu;
            const int hcol = j * 8 + u;
            const float* g0 = gsm + r * GS_STR;
            const float* g1 = g0 + BATCH * GS_STR;
            const float* g2 = g1 + BATCH * GS_STR;
            const float* g3 = g2 + BATCH * GS_STR;

            bool m = (__ldcg(&g_eos[cur][r]) != 0);
            const float* gpx = gx + (size_t)r * GDIM + hcol;
            float iv = g0[u]      + g1[u]      + g2[u]      + g3[u]      + __ldg(gpx);
            float fv = g0[8 + u]  + g1[8 + u]  + g2[8 + u]  + g3[8 + u]  + __ldg(gpx + HDIM);
            float gv = g0[16 + u] + g1[16 + u] + g2[16 + u] + g3[16 + u] + __ldg(gpx + 2 * HDIM);
            float ov = g0[24 + u] + g1[24 + u] + g2[24 + u] + g3[24 + u] + __ldg(gpx + 3 * HDIM);

            float cp  = __ldcg(cprev + (size_t)r * HDIM + hcol);
            float ncv = sigf(fv) * cp + sigf(iv) * tanhf(gv);
            float nhv = sigf(ov) * tanhf(ncv);

            ys[((size_t)t * BATCH + r) * HDIM + hcol] = nhv;   // unmasked, full fp32
            cnex[(size_t)r * HDIM + hcol] = m ? cp : ncv;
            // h state stored pre-quantized to tf32 (idempotent vs old cvt-at-load)
            float hq = m ? __ldcg(hprev + (size_t)r * HDIM + hcol)   // already quantized
                         : __uint_as_float(f2tf32(nhv));
            hnex[(size_t)r * HDIM + hcol] = hq;
        }

        if (blockIdx.x == 0 && tid < BATCH) {
            float xe = __ldg(X + ((size_t)t * BATCH + tid) * VDIM + 1);
            int eo = __ldcg(&g_eos[cur][tid]);
            g_eos[nxt][tid] = (eo != 0 || xe != 0.0f) ? 1 : 0;
        }

        grid_barrier();   // protects gsm/hs reuse and state hand-off
    }
}

// ---------------- launch ---------------------------------------------------
extern "C" void kernel_launch(void* const* d_in, const int* in_sizes, int n_in,
                              void* d_out, int out_size) {
    const float* x  = (const float*)d_in[0];
    const float* Wi = (const float*)d_in[1];
    const float* Wh = (const float*)d_in[2];
    const float* b  = (const float*)d_in[3];
    const float* c0 = (const float*)d_in[4];
    const float* h0 = (const float*)d_in[5];
    const unsigned char* eos0 = (const unsigned char*)d_in[6];
    float* ys = (float*)d_out;

    static bool attr_done = false;
    if (!attr_done) {
        cudaFuncSetAttribute(lstm_persist,
                             cudaFuncAttributeMaxDynamicSharedMemorySize, PSMEM_BYTES);
        attr_done = true;
    }

    init_state<<<(BATCH * HDIM + 255) / 256, 256>>>(c0, h0, eos0);

    dim3 g1(GDIM / G1_BN, (T_STEPS * BATCH) / G1_BM);   // 32 x 64
    gemm1<<<g1, 256>>>(x, Wi, b);

    lstm_persist<<<NCTA, NTHR, PSMEM_BYTES>>>(x, Wh, ys);
}